// round 16
// baseline (speedup 1.0000x reference)
#include <cuda_runtime.h>
#include <cuda_bf16.h>
#include <cstdint>
#include <math.h>

// Problem constants
#define BB 4
#define TT 2048
#define DD 512
#define HH 8
#define HD 64
#define BT (BB * TT)   // 8192
#define NQKV (3 * DD)  // 1536

// Scratch (device globals; NEVER pass their addresses from host code:
// GB300 ATS silently resolves the host shadow symbol to zeros).
__device__ __nv_bfloat16 g_Qh[BB * HH * TT * HD];
__device__ __nv_bfloat16 g_Ql[BB * HH * TT * HD];
__device__ __nv_bfloat16 g_Kh[BB * HH * TT * HD];
__device__ __nv_bfloat16 g_Kl[BB * HH * TT * HD];
__device__ __nv_bfloat16 g_Vh[BB * HH * TT * HD];
__device__ __nv_bfloat16 g_Vl[BB * HH * TT * HD];
__device__ __nv_bfloat16 gA_hi[BT * DD];     // A operand (x, then Y) split
__device__ __nv_bfloat16 gA_lo[BT * DD];
__device__ __nv_bfloat16 gBtQ_hi[NQKV * DD]; // Wqkv^T [1536][512]
__device__ __nv_bfloat16 gBtQ_lo[NQKV * DD];
__device__ __nv_bfloat16 gBtO_hi[DD * DD];   // Wout^T [512][512]
__device__ __nv_bfloat16 gBtO_lo[DD * DD];

// -------------------------- PTX helpers (sm_80-era, sm_103-safe) -----------
__device__ __forceinline__ uint32_t smem_u32(const void* p) {
    uint32_t a;
    asm("{ .reg .u64 t; cvta.to.shared.u64 t, %1; cvt.u32.u64 %0, t; }"
        : "=r"(a) : "l"(p));
    return a;
}
__device__ __forceinline__ void cp16(uint32_t s, const void* g) {
    asm volatile("cp.async.cg.shared.global [%0], [%1], 16;"
                 :: "r"(s), "l"(g));
}
#define CP_COMMIT() asm volatile("cp.async.commit_group;" ::: "memory")
#define CP_WAIT0()  asm volatile("cp.async.wait_group 0;" ::: "memory")
#define CP_WAIT1()  asm volatile("cp.async.wait_group 1;" ::: "memory")

__device__ __forceinline__ void ldsm4(uint32_t* r, uint32_t a) {
    asm volatile("ldmatrix.sync.aligned.m8n8.x4.shared.b16 {%0,%1,%2,%3}, [%4];"
                 : "=r"(r[0]), "=r"(r[1]), "=r"(r[2]), "=r"(r[3]) : "r"(a));
}
__device__ __forceinline__ void ldsm4t(uint32_t* r, uint32_t a) {
    asm volatile("ldmatrix.sync.aligned.m8n8.x4.trans.shared.b16 {%0,%1,%2,%3}, [%4];"
                 : "=r"(r[0]), "=r"(r[1]), "=r"(r[2]), "=r"(r[3]) : "r"(a));
}
// D += A(16x16 bf16, row) * B(16x8 bf16, col), fp32 accum
__device__ __forceinline__ void mma16816(float* c, const uint32_t* a,
                                         uint32_t b0, uint32_t b1) {
    asm volatile(
        "mma.sync.aligned.m16n8k16.row.col.f32.bf16.bf16.f32 "
        "{%0,%1,%2,%3}, {%4,%5,%6,%7}, {%8,%9}, {%0,%1,%2,%3};"
        : "+f"(c[0]), "+f"(c[1]), "+f"(c[2]), "+f"(c[3])
        : "r"(a[0]), "r"(a[1]), "r"(a[2]), "r"(a[3]), "r"(b0), "r"(b1));
}
// Swizzle for 128B rows (64 bf16 cols, 8 chunks of 16B): flash tiles.
__device__ __forceinline__ uint32_t swa(uint32_t base, int row, int chunk) {
    return base + row * 128 + ((chunk ^ (row & 7)) << 4);
}
// Swizzle for 64B rows (32 bf16 cols, 4 chunks of 16B): gemm KC=32 tiles.
__device__ __forceinline__ uint32_t swa32(uint32_t base, int row, int chunk) {
    return base + row * 64 + ((chunk ^ ((row >> 1) & 3)) << 4);
}
__device__ __forceinline__ uint32_t pack2(float x0, float x1) {
    __nv_bfloat162 v = __floats2bfloat162_rn(x0, x1);  // x0 -> low half
    return *(uint32_t*)&v;
}

// ---------------------------------------------------------------------------
// conv_all: single launch for all conversions.
//  blocks [0, 4096): resolve x vs mask per block, split x -> gA hi/lo
//  blocks [4096, 4096+1024): transpose+split Wqkv / Wout
// ---------------------------------------------------------------------------
#define XBLOCKS (BT * DD / 1024)   // 4096

__global__ __launch_bounds__(256) void conv_all(const float* __restrict__ a,
                                                const float* __restrict__ b,
                                                const float* __restrict__ Bq,
                                                const float* __restrict__ Bo) {
    if (blockIdx.x < XBLOCKS) {
        const float* src = a;
        if (b != nullptr) {
            int ca = __syncthreads_count(a[threadIdx.x] == 0.0f);
            int cb = __syncthreads_count(b[threadIdx.x] == 0.0f);
            src = (ca <= cb) ? a : b;
        }
        int idx = blockIdx.x * 256 + threadIdx.x;      // x4 elements
        float4 v = ((const float4*)src)[idx];
        __nv_bfloat16 h0 = __float2bfloat16(v.x), h1 = __float2bfloat16(v.y);
        __nv_bfloat16 h2 = __float2bfloat16(v.z), h3 = __float2bfloat16(v.w);
        uint32_t ph0 = pack2(v.x, v.y), ph1 = pack2(v.z, v.w);
        uint32_t pl0 = pack2(v.x - __bfloat162float(h0),
                             v.y - __bfloat162float(h1));
        uint32_t pl1 = pack2(v.z - __bfloat162float(h2),
                             v.w - __bfloat162float(h3));
        ((uint2*)gA_hi)[idx] = make_uint2(ph0, ph1);
        ((uint2*)gA_lo)[idx] = make_uint2(pl0, pl1);
        return;
    }
    // weight transpose+split: 1024 tile-blocks, 64 x-tiles x 16 k-tiles
    __shared__ float tile[32][33];
    int bid = blockIdx.x - XBLOCKS;
    int bx = bid & 63, by = bid >> 6;
    const bool isQ = bx < 48;
    const float* __restrict__ B = isQ ? Bq : Bo;
    const int N = isQ ? NQKV : DD;
    const int nBase = (isQ ? bx : bx - 48) * 32;
    const int kBase = by * 32;
    const int tx = threadIdx.x & 31, ty = threadIdx.x >> 5;
#pragma unroll
    for (int i = 0; i < 4; i++) {
        int row = ty + i * 8;
        tile[row][tx] = B[(size_t)(kBase + row) * N + nBase + tx];
    }
    __syncthreads();
    __nv_bfloat16* dh = isQ ? gBtQ_hi : gBtO_hi;
    __nv_bfloat16* dl = isQ ? gBtQ_lo : gBtO_lo;
#pragma unroll
    for (int i = 0; i < 4; i++) {
        int row = ty + i * 8;
        float v = tile[tx][row];
        __nv_bfloat16 h = __float2bfloat16(v);
        size_t o = (size_t)(nBase + row) * 512 + kBase + tx;
        dh[o] = h;
        dl[o] = __float2bfloat16(v - __bfloat162float(h));
    }
}

// ---------------------------------------------------------------------------
// HMMA GEMM: C[8192,NCOLS] = A @ Bt^T via 3-term split bf16 mma.sync.
// Tile 128x128, 8 warps (warp tile 64x32), K-chunks of 32, 3-stage cp.async
// ring (32KB/stage) -> 2 CTAs/SM. Single barrier per stage.
// A-fragment loads ROTATED under the previous mt's MMAs: only 2 mt fragment
// sets live (16 regs, was 32) and every LDSM is covered by >=12 MMAs.
// ---------------------------------------------------------------------------
#define GST 32768
#define NKC 16          // 512/32

template <int NCOLS, int SRC>
__global__ __launch_bounds__(256, 2) void gemm_mma(float* __restrict__ C) {
    extern __shared__ char sm_raw[];
    char* sm = (char*)((((uintptr_t)sm_raw) + 1023) & ~(uintptr_t)1023);
    const uint32_t uS0 = smem_u32(sm);

    const __nv_bfloat16* __restrict__ Bth = (SRC == 1) ? gBtQ_hi : gBtO_hi;
    const __nv_bfloat16* __restrict__ Btl = (SRC == 1) ? gBtQ_lo : gBtO_lo;

    const int tid = threadIdx.x, wid = tid >> 5, lane = tid & 31;
    const int wm = (wid >> 2) * 64;
    const int wn = (wid & 3) * 32;
    const int mBase = blockIdx.y * 128, nBase = blockIdx.x * 128;

    float acc[4][4][4] = {};                // [mtile16][ntile8][4]

    const int aLRow = lane & 15, aLChunk = lane >> 4;
    const int bLRow = (lane & 7) + ((lane >> 4) << 3);
    const int bLChunk = (lane >> 3) & 1;

    auto issue_chunk = [&](int kc, int st) {
        uint32_t base = uS0 + st * GST;
#pragma unroll
        for (int i = 0; i < 2; i++) {
            int idx = tid + i * 256;
            int row = idx >> 2, ch = idx & 3;
            uint32_t so = row * 64 + ((ch ^ ((row >> 1) & 3)) << 4);
            size_t ga = (size_t)(mBase + row) * 64 + kc * 4 + ch;
            size_t gb = (size_t)(nBase + row) * 64 + kc * 4 + ch;
            cp16(base + so,         (const uint4*)gA_hi + ga);
            cp16(base + 8192 + so,  (const uint4*)gA_lo + ga);
            cp16(base + 16384 + so, (const uint4*)Bth + gb);
            cp16(base + 24576 + so, (const uint4*)Btl + gb);
        }
    };

    issue_chunk(0, 0); CP_COMMIT();
    issue_chunk(1, 1); CP_COMMIT();

    for (int kc = 0; kc < NKC; kc++) {
        if (kc + 1 < NKC) CP_WAIT1(); else CP_WAIT0();
        __syncthreads();
        if (kc + 2 < NKC) { issue_chunk(kc + 2, (kc + 2) % 3); CP_COMMIT(); }

        const uint32_t uAh = uS0 + (kc % 3) * GST;
        const uint32_t uBh = uAh + 16384;
#pragma unroll
        for (int kk = 0; kk < 2; kk++) {    // 2 k16 steps per 32-chunk
            // B fragments (all 4 nt)
            uint32_t bh2[4][2], bl2[4][2];
#pragma unroll
            for (int np = 0; np < 2; np++) {
                uint32_t addr = swa32(uBh, wn + np * 16 + bLRow, kk * 2 + bLChunk);
                uint32_t r[4];
                ldsm4(r, addr);
                bh2[2 * np][0] = r[0]; bh2[2 * np][1] = r[1];
                bh2[2 * np + 1][0] = r[2]; bh2[2 * np + 1][1] = r[3];
                ldsm4(r, addr + 8192);
                bl2[2 * np][0] = r[0]; bl2[2 * np][1] = r[1];
                bl2[2 * np + 1][0] = r[2]; bl2[2 * np + 1][1] = r[3];
            }
            // A rotation: two fragment buffers; load mt+1 under mt's MMAs
            uint32_t ahA[4], alA[4], ahB[4], alB[4];
            {
                uint32_t a0 = swa32(uAh, wm + aLRow, kk * 2 + aLChunk);
                ldsm4(ahA, a0);
                ldsm4(alA, a0 + 8192);
            }
#pragma unroll
            for (int mt = 0; mt < 4; mt++) {
                uint32_t* ah = (mt & 1) ? ahB : ahA;
                uint32_t* al = (mt & 1) ? alB : alA;
                uint32_t* nah = (mt & 1) ? ahA : ahB;
                uint32_t* nal = (mt & 1) ? alA : alB;
                if (mt < 3) {
                    uint32_t ad = swa32(uAh, wm + (mt + 1) * 16 + aLRow,
                                        kk * 2 + aLChunk);
                    ldsm4(nah, ad);
                    ldsm4(nal, ad + 8192);
                }
#pragma unroll
                for (int nt = 0; nt < 4; nt++)
                    mma16816(acc[mt][nt], ah, bh2[nt][0], bh2[nt][1]);
#pragma unroll
                for (int nt = 0; nt < 4; nt++)
                    mma16816(acc[mt][nt], ah, bl2[nt][0], bl2[nt][1]);
#pragma unroll
                for (int nt = 0; nt < 4; nt++)
                    mma16816(acc[mt][nt], al, bh2[nt][0], bh2[nt][1]);
            }
        }
    }

    // Epilogue. c0,c1: row=lane>>2, cols cp,cp+1; c2,c3: row+8.
    const int rl = lane >> 2, cp = (lane & 3) * 2;
    const int which = (SRC == 1) ? (nBase >> 9) : 0;
    __nv_bfloat16* dsth = (which == 0) ? g_Qh : (which == 1) ? g_Kh : g_Vh;
    __nv_bfloat16* dstl = (which == 0) ? g_Ql : (which == 1) ? g_Kl : g_Vl;
#pragma unroll
    for (int mt = 0; mt < 4; mt++) {
#pragma unroll
        for (int half = 0; half < 2; half++) {
            int m = mBase + wm + mt * 16 + rl + half * 8;
#pragma unroll
            for (int nt = 0; nt < 4; nt++) {
                float v0 = acc[mt][nt][half * 2];
                float v1 = acc[mt][nt][half * 2 + 1];
                int n = nBase + wn + nt * 8 + cp;
                if (SRC == 1) {
                    int hh = (n & 511) >> 6, hd = n & 63;
                    int b = m >> 11, t = m & (TT - 1);
                    size_t o = ((size_t)((b * HH + hh) * TT + t)) * HD + hd;
                    __nv_bfloat16 h0 = __float2bfloat16(v0);
                    __nv_bfloat16 h1 = __float2bfloat16(v1);
                    *(uint32_t*)&dsth[o] = pack2(v0, v1);
                    *(uint32_t*)&dstl[o] = pack2(v0 - __bfloat162float(h0),
                                                 v1 - __bfloat162float(h1));
                } else {
                    *(float2*)(C + (size_t)m * NCOLS + n) = make_float2(v0, v1);
                }
            }
        }
    }
}

// ---------------------------------------------------------------------------
// HMMA flash attention (causal). BM=128 q x BN=64 kv, 8 warps x 16 rows.
// smem 96KB: Qh|Ql (32KB) + 2 KV stages (32KB each). Single barrier per
// tile. K fragments (S phase) and V fragments (PV phase) ROTATED: next
// group's ldmatrix issued before current group's MMAs.
// ---------------------------------------------------------------------------
#define FKV 32768

__global__ __launch_bounds__(256, 2) void flash_mma() {
    extern __shared__ char sm_raw[];
    char* sm = (char*)((((uintptr_t)sm_raw) + 1023) & ~(uintptr_t)1023);
    const uint32_t uQh = smem_u32(sm);
    const uint32_t uKV = uQh + 32768;

    const int tid = threadIdx.x, wid = tid >> 5, lane = tid & 31;
    const int bh = blockIdx.y;
    const int b = bh >> 3, h = bh & 7;
    const int qi = (int)(gridDim.x - 1) - (int)blockIdx.x;  // heavy first
    const int q0 = qi * 128;
    const size_t base4 = ((size_t)bh * TT * HD) >> 3;

    const int ldRow = tid >> 3, ldCh = tid & 7;

    auto issue_kv = [&](int j, int st) {
        uint32_t base = uKV + st * FKV;
#pragma unroll
        for (int i = 0; i < 2; i++) {
            int row = ldRow + i * 32;
            uint32_t so = row * 128 + ((ldCh ^ (row & 7)) << 4);
            size_t g = base4 + (size_t)(j * 64 + row) * 8 + ldCh;
            cp16(base + so,         (const uint4*)g_Kh + g);
            cp16(base + 8192 + so,  (const uint4*)g_Kl + g);
            cp16(base + 16384 + so, (const uint4*)g_Vh + g);
            cp16(base + 24576 + so, (const uint4*)g_Vl + g);
        }
    };

#pragma unroll
    for (int i = 0; i < 4; i++) {
        int row = ldRow + i * 32;
        uint32_t so = row * 128 + ((ldCh ^ (row & 7)) << 4);
        size_t g = base4 + (size_t)(q0 + row) * 8 + ldCh;
        cp16(uQh + so,         (const uint4*)g_Qh + g);
        cp16(uQh + 16384 + so, (const uint4*)g_Ql + g);
    }
    issue_kv(0, 0);
    CP_COMMIT();

    float m_[2] = {-1e30f, -1e30f}, l_[2] = {0.f, 0.f};
    float o[8][4] = {};

    const int aLRow = lane & 15, aLChunk = lane >> 4;
    const int bLRow = (lane & 7) + ((lane >> 4) << 3);
    const int bLChunk = (lane >> 3) & 1;
    const int vLRow = (lane & 7) + (((lane >> 3) & 1) << 3);
    const int vLChunk = lane >> 4;

    const int jmax = 2 * qi + 1;
    const int rowmax = q0 + wid * 16 + 15;
    const float C2 = 0.180336880f;          // 0.125 * log2(e)

    for (int j = 0; j <= jmax; j++) {
        CP_WAIT0();
        __syncthreads();
        if (j < jmax) { issue_kv(j + 1, (j + 1) & 1); CP_COMMIT(); }

        const int kv0 = j * 64;
        const bool needmask = (j >= 2 * qi);
        if (needmask && kv0 > rowmax) continue;

        const uint32_t uKh = uKV + (j & 1) * FKV;
        const uint32_t uVh = uKh + 16384;

        float s[8][4] = {};
#pragma unroll
        for (int kk = 0; kk < 4; kk++) {
            uint32_t qh[4], ql[4];
            uint32_t qa = swa(uQh, wid * 16 + aLRow, kk * 2 + aLChunk);
            ldsm4(qh, qa);
            ldsm4(ql, qa + 16384);
            // K rotation: load np+1 fragments before np's MMAs.
            uint32_t rhA[4], rlA[4], rhB[4], rlB[4];
            {
                uint32_t ka = swa(uKh, bLRow, kk * 2 + bLChunk);
                ldsm4(rhA, ka);
                ldsm4(rlA, ka + 8192);
            }
#pragma unroll
            for (int np = 0; np < 4; np++) {
                uint32_t* rh  = (np & 1) ? rhB : rhA;
                uint32_t* rl2 = (np & 1) ? rlB : rlA;
                uint32_t* nh  = (np & 1) ? rhA : rhB;
                uint32_t* nl  = (np & 1) ? rlA : rlB;
                if (np < 3) {
                    uint32_t ka = swa(uKh, (np + 1) * 16 + bLRow,
                                      kk * 2 + bLChunk);
                    ldsm4(nh, ka);
                    ldsm4(nl, ka + 8192);
                }
                if (needmask && kv0 + np * 16 > rowmax) continue;
                mma16816(s[2 * np],     qh, rh[0], rh[1]);
                mma16816(s[2 * np + 1], qh, rh[2], rh[3]);
                mma16816(s[2 * np],     qh, rl2[0], rl2[1]);
                mma16816(s[2 * np + 1], qh, rl2[2], rl2[3]);
                mma16816(s[2 * np],     ql, rh[0], rh[1]);
                mma16816(s[2 * np + 1], ql, rh[2], rh[3]);
            }
        }

        const int row0 = q0 + wid * 16 + (lane >> 2);
        if (needmask) {
#pragma unroll
            for (int nt = 0; nt < 8; nt++) {
                int col = kv0 + nt * 8 + (lane & 3) * 2;
#pragma unroll
                for (int i = 0; i < 4; i++)
                    if (col + (i & 1) > row0 + ((i >> 1) << 3))
                        s[nt][i] = -1e30f;
            }
        }

#pragma unroll
        for (int hh = 0; hh < 2; hh++) {
            float mx = -1e30f;
#pragma unroll
            for (int nt = 0; nt < 8; nt++)
                mx = fmaxf(mx, fmaxf(s[nt][hh * 2], s[nt][hh * 2 + 1]));
            mx = fmaxf(mx, __shfl_xor_sync(0xffffffffu, mx, 1));
            mx = fmaxf(mx, __shfl_xor_sync(0xffffffffu, mx, 2));
            float mnew = fmaxf(m_[hh], mx);
            float f = exp2f((m_[hh] - mnew) * C2);
            m_[hh] = mnew;
            float mc = mnew * C2;
            float sum = 0.f;
#pragma unroll
            for (int nt = 0; nt < 8; nt++) {
                float p0 = exp2f(fmaf(s[nt][hh * 2], C2, -mc));
                float p1 = exp2f(fmaf(s[nt][hh * 2 + 1], C2, -mc));
                s[nt][hh * 2] = p0; s[nt][hh * 2 + 1] = p1;
                sum += p0 + p1;
            }
            sum += __shfl_xor_sync(0xffffffffu, sum, 1);
            sum += __shfl_xor_sync(0xffffffffu, sum, 2);
            l_[hh] = l_[hh] * f + sum;
#pragma unroll
            for (int dt = 0; dt < 8; dt++) {
                o[dt][hh * 2] *= f; o[dt][hh * 2 + 1] *= f;
            }
        }

        // O += P V (skip fully-masked kv chunks; V fragments rotated over dp)
#pragma unroll
        for (int kk = 0; kk < 4; kk++) {
            if (needmask && kv0 + kk * 16 > rowmax) continue;
            const int j0 = 2 * kk, j1 = 2 * kk + 1;
            uint32_t aph[4], apl[4];
#pragma unroll
            for (int q = 0; q < 4; q++) {
                float x0 = (q < 2) ? s[j0][2 * q] : s[j1][2 * (q - 2)];
                float x1 = (q < 2) ? s[j0][2 * q + 1] : s[j1][2 * (q - 2) + 1];
                __nv_bfloat16 h0 = __float2bfloat16(x0);
                __nv_bfloat16 h1 = __float2bfloat16(x1);
                aph[q] = pack2(x0, x1);
                apl[q] = pack2(x0 - __bfloat162float(h0),
                               x1 - __bfloat162float(h1));
            }
            uint32_t rvA[4], rvlA[4], rvB[4], rvlB[4];
            {
                uint32_t va = swa(uVh, kk * 16 + vLRow, vLChunk);
                ldsm4t(rvA, va);
                ldsm4t(rvlA, va + 8192);
            }
#pragma unroll
            for (int dp = 0; dp < 4; dp++) {
                uint32_t* rv  = (dp & 1) ? rvB : rvA;
                uint32_t* rvl = (dp & 1) ? rvlB : rvlA;
                uint32_t* nv  = (dp & 1) ? rvA : rvB;
                uint32_t* nvl = (dp & 1) ? rvlA : rvlB;
                if (dp < 3) {
                    uint32_t va = swa(uVh, kk * 16 + vLRow,
                                      (dp + 1) * 2 + vLChunk);
                    ldsm4t(nv, va);
                    ldsm4t(nvl, va + 8192);
                }
                mma16816(o[2 * dp],     aph, rv[0], rv[1]);
                mma16816(o[2 * dp + 1], aph, rv[2], rv[3]);
                mma16816(o[2 * dp],     apl, rv[0], rv[1]);
                mma16816(o[2 * dp + 1], apl, rv[2], rv[3]);
                mma16816(o[2 * dp],     aph, rvl[0], rvl[1]);
                mma16816(o[2 * dp + 1], aph, rvl[2], rvl[3]);
            }
        }
    }

    const float inv0 = 1.0f / l_[0], inv1 = 1.0f / l_[1];
    const int t0 = q0 + wid * 16 + (lane >> 2);
#pragma unroll
    for (int dt = 0; dt < 8; dt++) {
        int d = dt * 8 + (lane & 3) * 2;
        size_t o0 = (size_t)(b * TT + t0) * DD + h * HD + d;
        size_t o1 = o0 + (size_t)8 * DD;
        float y0 = o[dt][0] * inv0, y1 = o[dt][1] * inv0;
        float y2 = o[dt][2] * inv1, y3 = o[dt][3] * inv1;
        __nv_bfloat16 h0 = __float2bfloat16(y0), h1 = __float2bfloat16(y1);
        __nv_bfloat16 h2 = __float2bfloat16(y2), h3 = __float2bfloat16(y3);
        *(uint32_t*)&gA_hi[o0] = pack2(y0, y1);
        *(uint32_t*)&gA_hi[o1] = pack2(y2, y3);
        *(uint32_t*)&gA_lo[o0] = pack2(y0 - __bfloat162float(h0),
                                       y1 - __bfloat162float(h1));
        *(uint32_t*)&gA_lo[o1] = pack2(y2 - __bfloat162float(h2),
                                       y3 - __bfloat162float(h3));
    }
}

// ---------------------------------------------------------------------------
// launch
// ---------------------------------------------------------------------------
extern "C" void kernel_launch(void* const* d_in, const int* in_sizes, int n_in,
                              void* d_out, int out_size) {
    const float* Wqkv = nullptr;
    const float* Wout = nullptr;
    const float* cand[2] = {nullptr, nullptr};
    int nc = 0;
    for (int i = 0; i < n_in; i++) {
        long sz = in_sizes[i];
        if (sz == 786432L) Wqkv = (const float*)d_in[i];
        else if (sz == 262144L) Wout = (const float*)d_in[i];
        else if (sz == 4194304L && nc < 2) cand[nc++] = (const float*)d_in[i];
    }
    if (!Wqkv && n_in > 2) Wqkv = (const float*)d_in[2];
    if (!Wout && n_in > 3) Wout = (const float*)d_in[3];
    if (!cand[0] && n_in > 0) cand[0] = (const float*)d_in[0];
    if (!cand[1] && n_in > 1 && cand[0] != (const float*)d_in[1])
        cand[1] = (const float*)d_in[1];

    float* out = (float*)d_out;

    const int GEMM_SMEM = 3 * GST + 1024;           // 99.25 KB
    const int FLASH_SMEM = 32768 + 2 * FKV + 1024;  // 97.25 KB
    cudaFuncSetAttribute(gemm_mma<NQKV, 1>,
                         cudaFuncAttributeMaxDynamicSharedMemorySize, GEMM_SMEM);
    cudaFuncSetAttribute(gemm_mma<DD, 2>,
                         cudaFuncAttributeMaxDynamicSharedMemorySize, GEMM_SMEM);
    cudaFuncSetAttribute(flash_mma,
                         cudaFuncAttributeMaxDynamicSharedMemorySize, FLASH_SMEM);

    conv_all<<<XBLOCKS + 1024, 256>>>(cand[0], cand[1], Wqkv, Wout);
    { dim3 grid(NQKV / 128, BT / 128); gemm_mma<NQKV, 1><<<grid, 256, GEMM_SMEM>>>(nullptr); }
    { dim3 grid(TT / 128, BB * HH); flash_mma<<<grid, 256, FLASH_SMEM>>>(); }
    { dim3 grid(DD / 128, BT / 128); gemm_mma<DD, 2><<<grid, 256, GEMM_SMEM>>>(out); }
}

// round 17
// speedup vs baseline: 1.0322x; 1.0322x over previous
#include <cuda_runtime.h>
#include <cuda_bf16.h>
#include <cstdint>
#include <math.h>

// Problem constants
#define BB 4
#define TT 2048
#define DD 512
#define HH 8
#define HD 64
#define BT (BB * TT)   // 8192
#define NQKV (3 * DD)  // 1536

// Scratch (device globals; NEVER pass their addresses from host code:
// GB300 ATS silently resolves the host shadow symbol to zeros).
__device__ __nv_bfloat16 g_Qh[BB * HH * TT * HD];
__device__ __nv_bfloat16 g_Ql[BB * HH * TT * HD];
__device__ __nv_bfloat16 g_Kh[BB * HH * TT * HD];
__device__ __nv_bfloat16 g_Kl[BB * HH * TT * HD];
__device__ __nv_bfloat16 g_Vh[BB * HH * TT * HD];
__device__ __nv_bfloat16 g_Vl[BB * HH * TT * HD];
__device__ __nv_bfloat16 gA_hi[BT * DD];     // A operand (x, then Y) split
__device__ __nv_bfloat16 gA_lo[BT * DD];
__device__ __nv_bfloat16 gBtQ_hi[NQKV * DD]; // Wqkv^T [1536][512]
__device__ __nv_bfloat16 gBtQ_lo[NQKV * DD];
__device__ __nv_bfloat16 gBtO_hi[DD * DD];   // Wout^T [512][512]
__device__ __nv_bfloat16 gBtO_lo[DD * DD];

// -------------------------- PTX helpers (sm_80-era, sm_103-safe) -----------
__device__ __forceinline__ uint32_t smem_u32(const void* p) {
    uint32_t a;
    asm("{ .reg .u64 t; cvta.to.shared.u64 t, %1; cvt.u32.u64 %0, t; }"
        : "=r"(a) : "l"(p));
    return a;
}
__device__ __forceinline__ void cp16(uint32_t s, const void* g) {
    asm volatile("cp.async.cg.shared.global [%0], [%1], 16;"
                 :: "r"(s), "l"(g));
}
#define CP_COMMIT() asm volatile("cp.async.commit_group;" ::: "memory")
#define CP_WAIT0()  asm volatile("cp.async.wait_group 0;" ::: "memory")
#define CP_WAIT1()  asm volatile("cp.async.wait_group 1;" ::: "memory")

__device__ __forceinline__ void ldsm4(uint32_t* r, uint32_t a) {
    asm volatile("ldmatrix.sync.aligned.m8n8.x4.shared.b16 {%0,%1,%2,%3}, [%4];"
                 : "=r"(r[0]), "=r"(r[1]), "=r"(r[2]), "=r"(r[3]) : "r"(a));
}
__device__ __forceinline__ void ldsm4t(uint32_t* r, uint32_t a) {
    asm volatile("ldmatrix.sync.aligned.m8n8.x4.trans.shared.b16 {%0,%1,%2,%3}, [%4];"
                 : "=r"(r[0]), "=r"(r[1]), "=r"(r[2]), "=r"(r[3]) : "r"(a));
}
// D += A(16x16 bf16, row) * B(16x8 bf16, col), fp32 accum
__device__ __forceinline__ void mma16816(float* c, const uint32_t* a,
                                         uint32_t b0, uint32_t b1) {
    asm volatile(
        "mma.sync.aligned.m16n8k16.row.col.f32.bf16.bf16.f32 "
        "{%0,%1,%2,%3}, {%4,%5,%6,%7}, {%8,%9}, {%0,%1,%2,%3};"
        : "+f"(c[0]), "+f"(c[1]), "+f"(c[2]), "+f"(c[3])
        : "r"(a[0]), "r"(a[1]), "r"(a[2]), "r"(a[3]), "r"(b0), "r"(b1));
}
// Swizzle for 128B rows (64 bf16 cols, 8 chunks of 16B): flash tiles.
__device__ __forceinline__ uint32_t swa(uint32_t base, int row, int chunk) {
    return base + row * 128 + ((chunk ^ (row & 7)) << 4);
}
// Swizzle for 64B rows (32 bf16 cols, 4 chunks of 16B): gemm KC=32 tiles.
__device__ __forceinline__ uint32_t swa32(uint32_t base, int row, int chunk) {
    return base + row * 64 + ((chunk ^ ((row >> 1) & 3)) << 4);
}
__device__ __forceinline__ uint32_t pack2(float x0, float x1) {
    __nv_bfloat162 v = __floats2bfloat162_rn(x0, x1);  // x0 -> low half
    return *(uint32_t*)&v;
}

// ---------------------------------------------------------------------------
// conv_all: single launch for all conversions.
//  blocks [0, 4096): resolve x vs mask per block, split x -> gA hi/lo
//  blocks [4096, 4096+1024): transpose+split Wqkv / Wout
// ---------------------------------------------------------------------------
#define XBLOCKS (BT * DD / 1024)   // 4096

__global__ __launch_bounds__(256) void conv_all(const float* __restrict__ a,
                                                const float* __restrict__ b,
                                                const float* __restrict__ Bq,
                                                const float* __restrict__ Bo) {
    if (blockIdx.x < XBLOCKS) {
        const float* src = a;
        if (b != nullptr) {
            int ca = __syncthreads_count(a[threadIdx.x] == 0.0f);
            int cb = __syncthreads_count(b[threadIdx.x] == 0.0f);
            src = (ca <= cb) ? a : b;
        }
        int idx = blockIdx.x * 256 + threadIdx.x;      // x4 elements
        float4 v = ((const float4*)src)[idx];
        __nv_bfloat16 h0 = __float2bfloat16(v.x), h1 = __float2bfloat16(v.y);
        __nv_bfloat16 h2 = __float2bfloat16(v.z), h3 = __float2bfloat16(v.w);
        uint32_t ph0 = pack2(v.x, v.y), ph1 = pack2(v.z, v.w);
        uint32_t pl0 = pack2(v.x - __bfloat162float(h0),
                             v.y - __bfloat162float(h1));
        uint32_t pl1 = pack2(v.z - __bfloat162float(h2),
                             v.w - __bfloat162float(h3));
        ((uint2*)gA_hi)[idx] = make_uint2(ph0, ph1);
        ((uint2*)gA_lo)[idx] = make_uint2(pl0, pl1);
        return;
    }
    // weight transpose+split: 1024 tile-blocks, 64 x-tiles x 16 k-tiles
    __shared__ float tile[32][33];
    int bid = blockIdx.x - XBLOCKS;
    int bx = bid & 63, by = bid >> 6;
    const bool isQ = bx < 48;
    const float* __restrict__ B = isQ ? Bq : Bo;
    const int N = isQ ? NQKV : DD;
    const int nBase = (isQ ? bx : bx - 48) * 32;
    const int kBase = by * 32;
    const int tx = threadIdx.x & 31, ty = threadIdx.x >> 5;
#pragma unroll
    for (int i = 0; i < 4; i++) {
        int row = ty + i * 8;
        tile[row][tx] = B[(size_t)(kBase + row) * N + nBase + tx];
    }
    __syncthreads();
    __nv_bfloat16* dh = isQ ? gBtQ_hi : gBtO_hi;
    __nv_bfloat16* dl = isQ ? gBtQ_lo : gBtO_lo;
#pragma unroll
    for (int i = 0; i < 4; i++) {
        int row = ty + i * 8;
        float v = tile[tx][row];
        __nv_bfloat16 h = __float2bfloat16(v);
        size_t o = (size_t)(nBase + row) * 512 + kBase + tx;
        dh[o] = h;
        dl[o] = __float2bfloat16(v - __bfloat162float(h));
    }
}

// ---------------------------------------------------------------------------
// HMMA GEMM (R16 measured-best): 128x128 tile, 8 warps, KC=32, 3-stage
// cp.async ring, single barrier per stage, A-fragment rotation.
// ---------------------------------------------------------------------------
#define GST 32768
#define NKC 16          // 512/32

template <int NCOLS, int SRC>
__global__ __launch_bounds__(256, 2) void gemm_mma(float* __restrict__ C) {
    extern __shared__ char sm_raw[];
    char* sm = (char*)((((uintptr_t)sm_raw) + 1023) & ~(uintptr_t)1023);
    const uint32_t uS0 = smem_u32(sm);

    const __nv_bfloat16* __restrict__ Bth = (SRC == 1) ? gBtQ_hi : gBtO_hi;
    const __nv_bfloat16* __restrict__ Btl = (SRC == 1) ? gBtQ_lo : gBtO_lo;

    const int tid = threadIdx.x, wid = tid >> 5, lane = tid & 31;
    const int wm = (wid >> 2) * 64;
    const int wn = (wid & 3) * 32;
    const int mBase = blockIdx.y * 128, nBase = blockIdx.x * 128;

    float acc[4][4][4] = {};                // [mtile16][ntile8][4]

    const int aLRow = lane & 15, aLChunk = lane >> 4;
    const int bLRow = (lane & 7) + ((lane >> 4) << 3);
    const int bLChunk = (lane >> 3) & 1;

    auto issue_chunk = [&](int kc, int st) {
        uint32_t base = uS0 + st * GST;
#pragma unroll
        for (int i = 0; i < 2; i++) {
            int idx = tid + i * 256;
            int row = idx >> 2, ch = idx & 3;
            uint32_t so = row * 64 + ((ch ^ ((row >> 1) & 3)) << 4);
            size_t ga = (size_t)(mBase + row) * 64 + kc * 4 + ch;
            size_t gb = (size_t)(nBase + row) * 64 + kc * 4 + ch;
            cp16(base + so,         (const uint4*)gA_hi + ga);
            cp16(base + 8192 + so,  (const uint4*)gA_lo + ga);
            cp16(base + 16384 + so, (const uint4*)Bth + gb);
            cp16(base + 24576 + so, (const uint4*)Btl + gb);
        }
    };

    issue_chunk(0, 0); CP_COMMIT();
    issue_chunk(1, 1); CP_COMMIT();

    for (int kc = 0; kc < NKC; kc++) {
        if (kc + 1 < NKC) CP_WAIT1(); else CP_WAIT0();
        __syncthreads();
        if (kc + 2 < NKC) { issue_chunk(kc + 2, (kc + 2) % 3); CP_COMMIT(); }

        const uint32_t uAh = uS0 + (kc % 3) * GST;
        const uint32_t uBh = uAh + 16384;
#pragma unroll
        for (int kk = 0; kk < 2; kk++) {    // 2 k16 steps per 32-chunk
            uint32_t bh2[4][2], bl2[4][2];
#pragma unroll
            for (int np = 0; np < 2; np++) {
                uint32_t addr = swa32(uBh, wn + np * 16 + bLRow, kk * 2 + bLChunk);
                uint32_t r[4];
                ldsm4(r, addr);
                bh2[2 * np][0] = r[0]; bh2[2 * np][1] = r[1];
                bh2[2 * np + 1][0] = r[2]; bh2[2 * np + 1][1] = r[3];
                ldsm4(r, addr + 8192);
                bl2[2 * np][0] = r[0]; bl2[2 * np][1] = r[1];
                bl2[2 * np + 1][0] = r[2]; bl2[2 * np + 1][1] = r[3];
            }
            // A rotation: two fragment buffers; load mt+1 under mt's MMAs
            uint32_t ahA[4], alA[4], ahB[4], alB[4];
            {
                uint32_t a0 = swa32(uAh, wm + aLRow, kk * 2 + aLChunk);
                ldsm4(ahA, a0);
                ldsm4(alA, a0 + 8192);
            }
#pragma unroll
            for (int mt = 0; mt < 4; mt++) {
                uint32_t* ah = (mt & 1) ? ahB : ahA;
                uint32_t* al = (mt & 1) ? alB : alA;
                uint32_t* nah = (mt & 1) ? ahA : ahB;
                uint32_t* nal = (mt & 1) ? alA : alB;
                if (mt < 3) {
                    uint32_t ad = swa32(uAh, wm + (mt + 1) * 16 + aLRow,
                                        kk * 2 + aLChunk);
                    ldsm4(nah, ad);
                    ldsm4(nal, ad + 8192);
                }
#pragma unroll
                for (int nt = 0; nt < 4; nt++)
                    mma16816(acc[mt][nt], ah, bh2[nt][0], bh2[nt][1]);
#pragma unroll
                for (int nt = 0; nt < 4; nt++)
                    mma16816(acc[mt][nt], ah, bl2[nt][0], bl2[nt][1]);
#pragma unroll
                for (int nt = 0; nt < 4; nt++)
                    mma16816(acc[mt][nt], al, bh2[nt][0], bh2[nt][1]);
            }
        }
    }

    // Epilogue. c0,c1: row=lane>>2, cols cp,cp+1; c2,c3: row+8.
    const int rl = lane >> 2, cp = (lane & 3) * 2;
    const int which = (SRC == 1) ? (nBase >> 9) : 0;
    __nv_bfloat16* dsth = (which == 0) ? g_Qh : (which == 1) ? g_Kh : g_Vh;
    __nv_bfloat16* dstl = (which == 0) ? g_Ql : (which == 1) ? g_Kl : g_Vl;
#pragma unroll
    for (int mt = 0; mt < 4; mt++) {
#pragma unroll
        for (int half = 0; half < 2; half++) {
            int m = mBase + wm + mt * 16 + rl + half * 8;
#pragma unroll
            for (int nt = 0; nt < 4; nt++) {
                float v0 = acc[mt][nt][half * 2];
                float v1 = acc[mt][nt][half * 2 + 1];
                int n = nBase + wn + nt * 8 + cp;
                if (SRC == 1) {
                    int hh = (n & 511) >> 6, hd = n & 63;
                    int b = m >> 11, t = m & (TT - 1);
                    size_t o = ((size_t)((b * HH + hh) * TT + t)) * HD + hd;
                    __nv_bfloat16 h0 = __float2bfloat16(v0);
                    __nv_bfloat16 h1 = __float2bfloat16(v1);
                    *(uint32_t*)&dsth[o] = pack2(v0, v1);
                    *(uint32_t*)&dstl[o] = pack2(v0 - __bfloat162float(h0),
                                                 v1 - __bfloat162float(h1));
                } else {
                    *(float2*)(C + (size_t)m * NCOLS + n) = make_float2(v0, v1);
                }
            }
        }
    }
}

// ---------------------------------------------------------------------------
// HMMA flash attention (R15 measured-best): BM=128 x BN=64, 8 warps x 16
// rows, 2-stage cp.async KV ring, single barrier per tile, causal skips in
// S and PV, exp2 fold, interleave-2 MMA order (NO fragment rotation).
// ---------------------------------------------------------------------------
#define FKV 32768

__global__ __launch_bounds__(256, 2) void flash_mma() {
    extern __shared__ char sm_raw[];
    char* sm = (char*)((((uintptr_t)sm_raw) + 1023) & ~(uintptr_t)1023);
    const uint32_t uQh = smem_u32(sm);
    const uint32_t uKV = uQh + 32768;

    const int tid = threadIdx.x, wid = tid >> 5, lane = tid & 31;
    const int bh = blockIdx.y;
    const int b = bh >> 3, h = bh & 7;
    const int qi = (int)(gridDim.x - 1) - (int)blockIdx.x;  // heavy first
    const int q0 = qi * 128;
    const size_t base4 = ((size_t)bh * TT * HD) >> 3;

    const int ldRow = tid >> 3, ldCh = tid & 7;

    auto issue_kv = [&](int j, int st) {
        uint32_t base = uKV + st * FKV;
#pragma unroll
        for (int i = 0; i < 2; i++) {
            int row = ldRow + i * 32;
            uint32_t so = row * 128 + ((ldCh ^ (row & 7)) << 4);
            size_t g = base4 + (size_t)(j * 64 + row) * 8 + ldCh;
            cp16(base + so,         (const uint4*)g_Kh + g);
            cp16(base + 8192 + so,  (const uint4*)g_Kl + g);
            cp16(base + 16384 + so, (const uint4*)g_Vh + g);
            cp16(base + 24576 + so, (const uint4*)g_Vl + g);
        }
    };

#pragma unroll
    for (int i = 0; i < 4; i++) {
        int row = ldRow + i * 32;
        uint32_t so = row * 128 + ((ldCh ^ (row & 7)) << 4);
        size_t g = base4 + (size_t)(q0 + row) * 8 + ldCh;
        cp16(uQh + so,         (const uint4*)g_Qh + g);
        cp16(uQh + 16384 + so, (const uint4*)g_Ql + g);
    }
    issue_kv(0, 0);
    CP_COMMIT();

    float m_[2] = {-1e30f, -1e30f}, l_[2] = {0.f, 0.f};
    float o[8][4] = {};

    const int aLRow = lane & 15, aLChunk = lane >> 4;
    const int bLRow = (lane & 7) + ((lane >> 4) << 3);
    const int bLChunk = (lane >> 3) & 1;
    const int vLRow = (lane & 7) + (((lane >> 3) & 1) << 3);
    const int vLChunk = lane >> 4;

    const int jmax = 2 * qi + 1;
    const int rowmax = q0 + wid * 16 + 15;
    const float C2 = 0.180336880f;          // 0.125 * log2(e)

    for (int j = 0; j <= jmax; j++) {
        CP_WAIT0();        // stage j (and Q on j=0) landed
        __syncthreads();   // visible to all; iter j-1 reads of stage j+1 done
        if (j < jmax) { issue_kv(j + 1, (j + 1) & 1); CP_COMMIT(); }

        const int kv0 = j * 64;
        const bool needmask = (j >= 2 * qi);
        if (needmask && kv0 > rowmax) continue;  // whole warp fully masked

        const uint32_t uKh = uKV + (j & 1) * FKV;
        const uint32_t uVh = uKh + 16384;

        float s[8][4] = {};
#pragma unroll
        for (int kk = 0; kk < 4; kk++) {
            uint32_t qh[4], ql[4];
            uint32_t qa = swa(uQh, wid * 16 + aLRow, kk * 2 + aLChunk);
            ldsm4(qh, qa);
            ldsm4(ql, qa + 16384);
#pragma unroll
            for (int np = 0; np < 4; np++) {
                if (needmask && kv0 + np * 16 > rowmax) continue;
                uint32_t rh[4], rl2[4];
                uint32_t ka = swa(uKh, np * 16 + bLRow, kk * 2 + bLChunk);
                ldsm4(rh, ka);
                ldsm4(rl2, ka + 8192);
                mma16816(s[2 * np],     qh, rh[0], rh[1]);
                mma16816(s[2 * np + 1], qh, rh[2], rh[3]);
                mma16816(s[2 * np],     qh, rl2[0], rl2[1]);
                mma16816(s[2 * np + 1], qh, rl2[2], rl2[3]);
                mma16816(s[2 * np],     ql, rh[0], rh[1]);
                mma16816(s[2 * np + 1], ql, rh[2], rh[3]);
            }
        }

        const int row0 = q0 + wid * 16 + (lane >> 2);
        if (needmask) {
#pragma unroll
            for (int nt = 0; nt < 8; nt++) {
                int col = kv0 + nt * 8 + (lane & 3) * 2;
#pragma unroll
                for (int i = 0; i < 4; i++)
                    if (col + (i & 1) > row0 + ((i >> 1) << 3))
                        s[nt][i] = -1e30f;
            }
        }

#pragma unroll
        for (int hh = 0; hh < 2; hh++) {
            float mx = -1e30f;
#pragma unroll
            for (int nt = 0; nt < 8; nt++)
                mx = fmaxf(mx, fmaxf(s[nt][hh * 2], s[nt][hh * 2 + 1]));
            mx = fmaxf(mx, __shfl_xor_sync(0xffffffffu, mx, 1));
            mx = fmaxf(mx, __shfl_xor_sync(0xffffffffu, mx, 2));
            float mnew = fmaxf(m_[hh], mx);
            float f = exp2f((m_[hh] - mnew) * C2);
            m_[hh] = mnew;
            float mc = mnew * C2;
            float sum = 0.f;
#pragma unroll
            for (int nt = 0; nt < 8; nt++) {
                float p0 = exp2f(fmaf(s[nt][hh * 2], C2, -mc));
                float p1 = exp2f(fmaf(s[nt][hh * 2 + 1], C2, -mc));
                s[nt][hh * 2] = p0; s[nt][hh * 2 + 1] = p1;
                sum += p0 + p1;
            }
            sum += __shfl_xor_sync(0xffffffffu, sum, 1);
            sum += __shfl_xor_sync(0xffffffffu, sum, 2);
            l_[hh] = l_[hh] * f + sum;
#pragma unroll
            for (int dt = 0; dt < 8; dt++) {
                o[dt][hh * 2] *= f; o[dt][hh * 2 + 1] *= f;
            }
        }

        // O += P V (skip fully-masked kv chunks: their P is all 0)
#pragma unroll
        for (int kk = 0; kk < 4; kk++) {
            if (needmask && kv0 + kk * 16 > rowmax) continue;
            const int j0 = 2 * kk, j1 = 2 * kk + 1;
            uint32_t aph[4], apl[4];
#pragma unroll
            for (int q = 0; q < 4; q++) {
                float x0 = (q < 2) ? s[j0][2 * q] : s[j1][2 * (q - 2)];
                float x1 = (q < 2) ? s[j0][2 * q + 1] : s[j1][2 * (q - 2) + 1];
                __nv_bfloat16 h0 = __float2bfloat16(x0);
                __nv_bfloat16 h1 = __float2bfloat16(x1);
                aph[q] = pack2(x0, x1);
                apl[q] = pack2(x0 - __bfloat162float(h0),
                               x1 - __bfloat162float(h1));
            }
#pragma unroll
            for (int dp = 0; dp < 4; dp++) {
                uint32_t rv[4], rvl[4];
                uint32_t va = swa(uVh, kk * 16 + vLRow, dp * 2 + vLChunk);
                ldsm4t(rv, va);
                ldsm4t(rvl, va + 8192);
                mma16816(o[2 * dp],     aph, rv[0], rv[1]);
                mma16816(o[2 * dp + 1], aph, rv[2], rv[3]);
                mma16816(o[2 * dp],     apl, rv[0], rv[1]);
                mma16816(o[2 * dp + 1], apl, rv[2], rv[3]);
                mma16816(o[2 * dp],     aph, rvl[0], rvl[1]);
                mma16816(o[2 * dp + 1], aph, rvl[2], rvl[3]);
            }
        }
    }

    const float inv0 = 1.0f / l_[0], inv1 = 1.0f / l_[1];
    const int t0 = q0 + wid * 16 + (lane >> 2);
#pragma unroll
    for (int dt = 0; dt < 8; dt++) {
        int d = dt * 8 + (lane & 3) * 2;
        size_t o0 = (size_t)(b * TT + t0) * DD + h * HD + d;
        size_t o1 = o0 + (size_t)8 * DD;
        float y0 = o[dt][0] * inv0, y1 = o[dt][1] * inv0;
        float y2 = o[dt][2] * inv1, y3 = o[dt][3] * inv1;
        __nv_bfloat16 h0 = __float2bfloat16(y0), h1 = __float2bfloat16(y1);
        __nv_bfloat16 h2 = __float2bfloat16(y2), h3 = __float2bfloat16(y3);
        *(uint32_t*)&gA_hi[o0] = pack2(y0, y1);
        *(uint32_t*)&gA_hi[o1] = pack2(y2, y3);
        *(uint32_t*)&gA_lo[o0] = pack2(y0 - __bfloat162float(h0),
                                       y1 - __bfloat162float(h1));
        *(uint32_t*)&gA_lo[o1] = pack2(y2 - __bfloat162float(h2),
                                       y3 - __bfloat162float(h3));
    }
}

// ---------------------------------------------------------------------------
// launch
// ---------------------------------------------------------------------------
extern "C" void kernel_launch(void* const* d_in, const int* in_sizes, int n_in,
                              void* d_out, int out_size) {
    const float* Wqkv = nullptr;
    const float* Wout = nullptr;
    const float* cand[2] = {nullptr, nullptr};
    int nc = 0;
    for (int i = 0; i < n_in; i++) {
        long sz = in_sizes[i];
        if (sz == 786432L) Wqkv = (const float*)d_in[i];
        else if (sz == 262144L) Wout = (const float*)d_in[i];
        else if (sz == 4194304L && nc < 2) cand[nc++] = (const float*)d_in[i];
    }
    if (!Wqkv && n_in > 2) Wqkv = (const float*)d_in[2];
    if (!Wout && n_in > 3) Wout = (const float*)d_in[3];
    if (!cand[0] && n_in > 0) cand[0] = (const float*)d_in[0];
    if (!cand[1] && n_in > 1 && cand[0] != (const float*)d_in[1])
        cand[1] = (const float*)d_in[1];

    float* out = (float*)d_out;

    const int GEMM_SMEM = 3 * GST + 1024;           // 99.25 KB
    const int FLASH_SMEM = 32768 + 2 * FKV + 1024;  // 97.25 KB
    cudaFuncSetAttribute(gemm_mma<NQKV, 1>,
                         cudaFuncAttributeMaxDynamicSharedMemorySize, GEMM_SMEM);
    cudaFuncSetAttribute(gemm_mma<DD, 2>,
                         cudaFuncAttributeMaxDynamicSharedMemorySize, GEMM_SMEM);
    cudaFuncSetAttribute(flash_mma,
                         cudaFuncAttributeMaxDynamicSharedMemorySize, FLASH_SMEM);

    conv_all<<<XBLOCKS + 1024, 256>>>(cand[0], cand[1], Wqkv, Wout);
    { dim3 grid(NQKV / 128, BT / 128); gemm_mma<NQKV, 1><<<grid, 256, GEMM_SMEM>>>(nullptr); }
    { dim3 grid(TT / 128, BB * HH); flash_mma<<<grid, 256, FLASH_SMEM>>>(); }
    { dim3 grid(DD / 128, BT / 128); gemm_mma<DD, 2><<<grid, 256, GEMM_SMEM>>>(out); }
}